// round 4
// baseline (speedup 1.0000x reference)
#include <cuda_runtime.h>
#include <cuda_bf16.h>
#include <cstdint>

#define GNX 512
#define GNY 512
#define GP (GNX * GNY)        // 262144 pillars
#define GB 4
#define GNPTS 100000
#define GC 64

// 4 * 262144 * 64 floats = 256 MB scratch, zero-initialized at module load.
// Re-zeroed by the transpose kernel on every call (write-zero-behind),
// so each kernel_launch invocation starts from zeros. No runtime allocation.
__device__ float g_scratch[(size_t)GB * GP * GC];

// ---------------------------------------------------------------------------
// Pass 1: scatter-add points into (B, P, C) scratch.
// 16 threads per point; each thread loads a float4 of x (coalesced: x is
// (B, N, C) with C contiguous) and issues 4 contiguous atomicAdds.
// A point's 64 adds cover 256 contiguous bytes => 8 full 32B sectors.
// NOTE: indices are int32 on the wire (JAX x64-disabled downgrades the
// reference's int64 request to int32).
// ---------------------------------------------------------------------------
__global__ void scatter_kernel(const float* __restrict__ x,
                               const int* __restrict__ indices) {
    unsigned t = blockIdx.x * blockDim.x + threadIdx.x;
    const unsigned total = GB * GNPTS * (GC / 4);  // 6.4M threads
    if (t >= total) return;

    unsigned point = t >> 4;          // which (b, n)
    unsigned c4    = (t & 15u) << 2;  // channel group start
    unsigned b     = point / GNPTS;

    int p = indices[point];           // broadcast across the 16 threads (L1 hit)
    if (p < 0 || p >= GP) return;     // defensive: never crash on bad dtype

    float4 v = *reinterpret_cast<const float4*>(x + (size_t)point * GC + c4);

    float* dst = g_scratch + ((size_t)b * GP + (size_t)p) * GC + c4;
    atomicAdd(dst + 0, v.x);
    atomicAdd(dst + 1, v.y);
    atomicAdd(dst + 2, v.z);
    atomicAdd(dst + 3, v.w);
}

// ---------------------------------------------------------------------------
// Pass 2: transpose (B, P, C) -> (B, C, P) through a padded shared tile,
// zeroing scratch behind the read (free re-init: same dirty line).
// Block = 32x32 threads; grid = (P/32, C/32, B).
// Reads coalesced along c, writes coalesced along p.
// ---------------------------------------------------------------------------
__global__ void transpose_zero_kernel(float* __restrict__ out) {
    __shared__ float tile[32][33];

    unsigned p0 = blockIdx.x << 5;
    unsigned c0 = blockIdx.y << 5;
    unsigned b  = blockIdx.z;
    unsigned tx = threadIdx.x;
    unsigned ty = threadIdx.y;

    size_t sidx = ((size_t)b * GP + p0 + ty) * GC + c0 + tx;
    tile[ty][tx] = g_scratch[sidx];
    g_scratch[sidx] = 0.0f;           // re-zero for next invocation

    __syncthreads();

    out[((size_t)b * GC + c0 + ty) * GP + p0 + tx] = tile[tx][ty];
}

extern "C" void kernel_launch(void* const* d_in, const int* in_sizes, int n_in,
                              void* d_out, int out_size) {
    const float* x   = (const float*)d_in[0];   // (B, N, C) fp32
    const int*   idx = (const int*)d_in[1];     // (B, N) int32 (see note above)
    float*       out = (float*)d_out;           // (B, C, NX, NY) fp32

    (void)in_sizes; (void)n_in; (void)out_size;

    const unsigned total = GB * GNPTS * (GC / 4);
    scatter_kernel<<<(total + 255) / 256, 256>>>(x, idx);

    dim3 tgrid(GP / 32, GC / 32, GB);
    dim3 tblock(32, 32);
    transpose_zero_kernel<<<tgrid, tblock>>>(out);
}

// round 5
// speedup vs baseline: 12.9395x; 12.9395x over previous
#include <cuda_runtime.h>
#include <cuda_bf16.h>
#include <cstdint>

#define GNX 512
#define GNY 512
#define GP (GNX * GNY)        // 262144 pillars
#define GB 4
#define GNPTS 100000
#define GC 64

// 256 MB scratch, (B, P, C). Zeroed explicitly by zero_kernel each call.
__device__ __align__(256) float g_scratch[(size_t)GB * GP * GC];

// ---------------------------------------------------------------------------
// Pass 0: zero the scratch. Pure streaming STG.128, grid-stride, MLP-deep.
// ---------------------------------------------------------------------------
__global__ void zero_kernel() {
    const size_t n4 = (size_t)GB * GP * GC / 4;   // 16.78M float4
    float4* s = (float4*)g_scratch;
    float4 z = make_float4(0.f, 0.f, 0.f, 0.f);
    size_t stride = (size_t)gridDim.x * blockDim.x;
    for (size_t k = (size_t)blockIdx.x * blockDim.x + threadIdx.x; k < n4; k += stride)
        s[k] = z;
}

// ---------------------------------------------------------------------------
// Pass 1: scatter-add points into (B, P, C) scratch.
// 16 threads per point; float4 coalesced reads of x, 4 contiguous atomicAdds
// (full 32B sectors per point). Indices are int32 on the wire (JAX x64-off).
// ---------------------------------------------------------------------------
__global__ void scatter_kernel(const float* __restrict__ x,
                               const int* __restrict__ indices) {
    unsigned t = blockIdx.x * blockDim.x + threadIdx.x;
    const unsigned total = GB * GNPTS * (GC / 4);  // 6.4M threads
    if (t >= total) return;

    unsigned point = t >> 4;
    unsigned c4    = (t & 15u) << 2;
    unsigned b     = point / GNPTS;

    int p = indices[point];
    if (p < 0 || p >= GP) return;  // defensive

    float4 v = *reinterpret_cast<const float4*>(x + (size_t)point * GC + c4);

    float* dst = g_scratch + ((size_t)b * GP + (size_t)p) * GC + c4;
    atomicAdd(dst + 0, v.x);
    atomicAdd(dst + 1, v.y);
    atomicAdd(dst + 2, v.z);
    atomicAdd(dst + 3, v.w);
}

// ---------------------------------------------------------------------------
// Pass 2: transpose (B, P, C) -> (B, C, P).
// 64x64 tile per block (16.25 KB smem incl. pad), 256 threads.
// Each thread: 4 independent LDG.128 (MLP=4), then 4 STG.128.
// Warp-level: loads are 512 B contiguous per instruction; stores are 256 B
// contiguous per channel row. Smem pad of 1 float keeps column reads ~2-way.
// ---------------------------------------------------------------------------
__global__ void transpose_kernel(float* __restrict__ out) {
    __shared__ float tile[64][65];

    unsigned b  = blockIdx.y;
    unsigned p0 = blockIdx.x << 6;          // 64 pillars per block
    unsigned tid = threadIdx.x;             // 0..255

    const float4* src = reinterpret_cast<const float4*>(
        g_scratch + ((size_t)b * GP + p0) * GC);

#pragma unroll
    for (int i = 0; i < 4; i++) {
        unsigned f    = tid + i * 256;      // 0..1023 float4s in tile
        unsigned row  = f >> 4;             // pillar within tile
        unsigned col4 = f & 15u;            // channel group
        float4 v = src[row * 16 + col4];
        tile[row][col4 * 4 + 0] = v.x;
        tile[row][col4 * 4 + 1] = v.y;
        tile[row][col4 * 4 + 2] = v.z;
        tile[row][col4 * 4 + 3] = v.w;
    }
    __syncthreads();

#pragma unroll
    for (int i = 0; i < 4; i++) {
        unsigned o = tid + i * 256;
        unsigned c = o >> 4;                // channel
        unsigned q = o & 15u;               // pillar chunk (4 pillars)
        float4 v = make_float4(tile[q * 4 + 0][c],
                               tile[q * 4 + 1][c],
                               tile[q * 4 + 2][c],
                               tile[q * 4 + 3][c]);
        *reinterpret_cast<float4*>(
            out + ((size_t)b * GC + c) * GP + p0 + q * 4) = v;
    }
}

extern "C" void kernel_launch(void* const* d_in, const int* in_sizes, int n_in,
                              void* d_out, int out_size) {
    const float* x   = (const float*)d_in[0];   // (B, N, C) fp32
    const int*   idx = (const int*)d_in[1];     // (B, N) int32
    float*       out = (float*)d_out;           // (B, C, NX, NY) fp32

    (void)in_sizes; (void)n_in; (void)out_size;

    zero_kernel<<<16384, 256>>>();

    const unsigned total = GB * GNPTS * (GC / 4);
    scatter_kernel<<<(total + 255) / 256, 256>>>(x, idx);

    dim3 tgrid(GP / 64, GB);
    transpose_kernel<<<tgrid, 256>>>(out);
}

// round 6
// speedup vs baseline: 19.8603x; 1.5349x over previous
#include <cuda_runtime.h>
#include <cuda_bf16.h>
#include <cstdint>

#define GNX 512
#define GNY 512
#define GP (GNX * GNY)          // 262144 pillars
#define GB 4
#define GNPTS 100000
#define GC 64
#define TILE_P 64               // pillars per tile
#define TILES_PER_B (GP / TILE_P)   // 4096
#define NTILES (GB * TILES_PER_B)   // 16384
#define NPTS_TOTAL (GB * GNPTS)     // 400000

// Small CSR buffers (≈1.8 MB total) — no 256 MB dense scratch.
__device__ int      g_hist[NTILES];
__device__ int      g_off[NTILES + 1];
__device__ int      g_cursor[NTILES];
__device__ unsigned g_list[NPTS_TOTAL];

// ---------------------------------------------------------------------------
// K1: zero tile histogram (64 KB)
// ---------------------------------------------------------------------------
__global__ void zero_hist_kernel() {
    int i = blockIdx.x * blockDim.x + threadIdx.x;
    if (i < NTILES) g_hist[i] = 0;
}

// ---------------------------------------------------------------------------
// K2: per-tile histogram. indices are int32 on the wire (JAX x64-off).
// ---------------------------------------------------------------------------
__global__ void hist_kernel(const int* __restrict__ indices) {
    int t = blockIdx.x * blockDim.x + threadIdx.x;
    if (t >= NPTS_TOTAL) return;
    int b = t / GNPTS;
    int p = indices[t];
    if (p < 0 || p >= GP) return;  // defensive
    atomicAdd(&g_hist[b * TILES_PER_B + (p >> 6)], 1);
}

// ---------------------------------------------------------------------------
// K3: single-block exclusive scan of 16384 counters (1024 thr x 16 elems).
// Writes g_off (exclusive) and seeds g_cursor.
// ---------------------------------------------------------------------------
__global__ void scan_kernel() {
    __shared__ int warp_sums[32];
    int tid  = threadIdx.x;
    int lane = tid & 31, wid = tid >> 5;
    int base = tid * 16;

    int vals[16];
    int s = 0;
#pragma unroll
    for (int i = 0; i < 16; i++) { vals[i] = g_hist[base + i]; s += vals[i]; }

    // inclusive warp scan of per-thread sums
    int inc = s;
#pragma unroll
    for (int o = 1; o < 32; o <<= 1) {
        int v = __shfl_up_sync(0xFFFFFFFFu, inc, o);
        if (lane >= o) inc += v;
    }
    if (lane == 31) warp_sums[wid] = inc;
    __syncthreads();
    if (wid == 0) {
        int w = warp_sums[lane];
#pragma unroll
        for (int o = 1; o < 32; o <<= 1) {
            int v = __shfl_up_sync(0xFFFFFFFFu, w, o);
            if (lane >= o) w += v;
        }
        warp_sums[lane] = w;
    }
    __syncthreads();

    int excl = ((wid == 0) ? 0 : warp_sums[wid - 1]) + (inc - s);
    int run = excl;
#pragma unroll
    for (int i = 0; i < 16; i++) {
        g_off[base + i]    = run;
        g_cursor[base + i] = run;
        run += vals[i];
    }
    if (tid == 1023) g_off[NTILES] = run;
}

// ---------------------------------------------------------------------------
// K4: fill point list. entry = (pillar & 63) << 20 | global_point_id.
// Entries of one tile are contiguous in g_list (cursor starts at off[tile]).
// ---------------------------------------------------------------------------
__global__ void fill_kernel(const int* __restrict__ indices) {
    int t = blockIdx.x * blockDim.x + threadIdx.x;
    if (t >= NPTS_TOTAL) return;
    int b = t / GNPTS;
    int p = indices[t];
    if (p < 0 || p >= GP) return;
    int tile = b * TILES_PER_B + (p >> 6);
    int pos = atomicAdd(&g_cursor[tile], 1);
    g_list[pos] = ((unsigned)(p & 63) << 20) | (unsigned)t;
}

// ---------------------------------------------------------------------------
// K5: gather + accumulate + write. One block per 64-pillar tile.
// Warp per point: 32 lanes read the 256B feature row as coalesced float2,
// smem-atomicAdd into acc[c][p] (pad 65 -> 2-way worst-case conflicts).
// Then stream the 16 KB (64c x 64p) tile to out, fully coalesced.
// ---------------------------------------------------------------------------
__global__ void gather_kernel(const float* __restrict__ x,
                              float* __restrict__ out) {
    __shared__ float acc[GC][TILE_P + 1];

    int tid = threadIdx.x;
    for (int i = tid; i < GC * (TILE_P + 1); i += 256)
        ((float*)acc)[i] = 0.0f;
    __syncthreads();

    int tile  = blockIdx.x;
    int start = g_off[tile];
    int end   = g_off[tile + 1];
    int wid   = tid >> 5;
    int lane  = tid & 31;

    for (int e = start + wid; e < end; e += 8) {
        unsigned ent = g_list[e];
        unsigned gid = ent & 0xFFFFFu;
        unsigned plo = ent >> 20;
        float2 v = reinterpret_cast<const float2*>(x + (size_t)gid * GC)[lane];
        atomicAdd(&acc[2 * lane + 0][plo], v.x);
        atomicAdd(&acc[2 * lane + 1][plo], v.y);
    }
    __syncthreads();

    int b  = tile >> 12;                 // tile / TILES_PER_B
    int p0 = (tile & (TILES_PER_B - 1)) << 6;
    float* obase = out + ((size_t)b * GC) * GP + p0;

    for (int i = tid; i < GC * (TILE_P / 4); i += 256) {
        int c = i >> 4;
        int q = (i & 15) << 2;
        float4 v = make_float4(acc[c][q], acc[c][q + 1], acc[c][q + 2], acc[c][q + 3]);
        *reinterpret_cast<float4*>(obase + (size_t)c * GP + q) = v;
    }
}

extern "C" void kernel_launch(void* const* d_in, const int* in_sizes, int n_in,
                              void* d_out, int out_size) {
    const float* x   = (const float*)d_in[0];   // (B, N, C) fp32
    const int*   idx = (const int*)d_in[1];     // (B, N) int32
    float*       out = (float*)d_out;           // (B, C, NX, NY) fp32

    (void)in_sizes; (void)n_in; (void)out_size;

    zero_hist_kernel<<<NTILES / 1024, 1024>>>();
    hist_kernel<<<(NPTS_TOTAL + 255) / 256, 256>>>(idx);
    scan_kernel<<<1, 1024>>>();
    fill_kernel<<<(NPTS_TOTAL + 255) / 256, 256>>>(idx);
    gather_kernel<<<NTILES, 256>>>(x, out);
}